// round 3
// baseline (speedup 1.0000x reference)
#include <cuda_runtime.h>

#define BATCH 8
#define NN 2048
#define IN_DIM 128
#define OUT_DIM 64
#define NEG_SLOPE 0.2f

// Scratch (allocation-free rule: __device__ globals)
__device__ float g_h[BATCH * NN * OUT_DIM];   // 4 MB
__device__ float g_fi[BATCH * NN];
__device__ float g_fj[BATCH * NN];

// ---- packed f32x2 helpers (ptxas never emits FFMA2 from C++) ----
__device__ __forceinline__ unsigned long long pack2(float x, float y) {
    unsigned long long r;
    asm("mov.b64 %0, {%1, %2};" : "=l"(r) : "f"(x), "f"(y));
    return r;
}
__device__ __forceinline__ void unpack2(unsigned long long v, float& x, float& y) {
    asm("mov.b64 {%0, %1}, %2;" : "=f"(x), "=f"(y) : "l"(v));
}
__device__ __forceinline__ void ffma2(unsigned long long& d, unsigned long long a, unsigned long long b) {
    asm("fma.rn.f32x2 %0, %1, %2, %0;" : "+l"(d) : "l"(a), "l"(b));
}

__device__ __forceinline__ float neg_inf_f() { return __int_as_float(0xff800000); }

// ============================================================================
// Kernel A: h = x @ W (fp32), f_i = h·a[:64], f_j = h·a[64:]
// One block = 32 rows, 256 threads, each thread: 1 row x 8 dims.
// ============================================================================
__global__ void __launch_bounds__(256) gat_h_kernel(
    const float* __restrict__ x, const float* __restrict__ W, const float* __restrict__ a)
{
    __shared__ float W_s[IN_DIM * OUT_DIM];  // 32 KB
    int tid = threadIdx.x;
    {
        const float4* Wv = (const float4*)W;
        float4* Wsv = (float4*)W_s;
#pragma unroll
        for (int i = 0; i < 8; i++) Wsv[tid + i * 256] = Wv[tid + i * 256];
    }
    __syncthreads();

    int r = tid >> 3;            // 0..31 row within block
    int dg = (tid & 7) * 8;      // dim group start
    int row = blockIdx.x * 32 + r;
    const float* xrow = x + (size_t)row * IN_DIM;

    float acc[8];
#pragma unroll
    for (int d = 0; d < 8; d++) acc[d] = 0.0f;

#pragma unroll 4
    for (int k = 0; k < IN_DIM; k++) {
        float xv = __ldg(&xrow[k]);            // broadcast among the 8 dim-group threads
        const float* wr = &W_s[k * OUT_DIM + dg];
#pragma unroll
        for (int d = 0; d < 8; d++) acc[d] = fmaf(xv, wr[d], acc[d]);
    }

    // write h (two float4 per thread, contiguous per warp)
    size_t hbase = (size_t)row * OUT_DIM + dg;
    *(float4*)&g_h[hbase]     = make_float4(acc[0], acc[1], acc[2], acc[3]);
    *(float4*)&g_h[hbase + 4] = make_float4(acc[4], acc[5], acc[6], acc[7]);

    // partial dots with a_i / a_j, reduce across the 8 threads of this row
    float fi = 0.0f, fj = 0.0f;
#pragma unroll
    for (int d = 0; d < 8; d++) {
        fi = fmaf(acc[d], __ldg(&a[dg + d]), fi);
        fj = fmaf(acc[d], __ldg(&a[OUT_DIM + dg + d]), fj);
    }
#pragma unroll
    for (int off = 4; off > 0; off >>= 1) {
        fi += __shfl_down_sync(0xffffffffu, fi, off);
        fj += __shfl_down_sync(0xffffffffu, fj, off);
    }
    if ((tid & 7) == 0) {
        g_fi[row] = fi;
        g_fj[row] = fj;
    }
}

// ============================================================================
// Kernel C: per (i-tile of 64 rows, batch): softmax stats (2 sweeps), then
// tiled alpha computation + write + out accumulation with f32x2 FFMA.
// Grid: (32, 8), 256 threads. Static SMEM ~42 KB.
// ============================================================================
__global__ void __launch_bounds__(256) gat_main_kernel(
    const float* __restrict__ adj, float* __restrict__ out, float* __restrict__ alpha_out)
{
    __shared__ float fj_s[NN];            // 8 KB
    __shared__ float fi_s[64];
    __shared__ float m_s[64];
    __shared__ float sinv_s[64];
    __shared__ float h_s[64 * OUT_DIM];   // 16 KB   (j-tile of h)
    __shared__ float alpha_t[64 * 65];    // 16.25 KB, stride-65 padded (transposed alpha tile)

    int tid  = threadIdx.x;
    int lane = tid & 31;
    int w    = tid >> 5;                  // 8 warps
    int b    = blockIdx.y;
    int i0   = blockIdx.x * 64;

    // load f_j (full batch row) and f_i tile
    for (int j = tid; j < NN; j += 256) fj_s[j] = g_fj[b * NN + j];
    if (tid < 64) fi_s[tid] = g_fi[b * NN + i0 + tid];
    __syncthreads();

    // ---- Pass 1: per-row masked max, then sum of exp (adj stays hot in L1) ----
#pragma unroll 1
    for (int rr = 0; rr < 8; rr++) {
        int r = w * 8 + rr;
        const float* adjrow = adj + (size_t)(i0 + r) * NN;
        float fi = fi_s[r];

        float m = neg_inf_f();
#pragma unroll 1
        for (int j = lane; j < NN; j += 128) {
            float a0 = adjrow[j];
            float a1 = adjrow[j + 32];
            float a2 = adjrow[j + 64];
            float a3 = adjrow[j + 96];
            float z0 = fi + fj_s[j];      z0 = fmaxf(z0, NEG_SLOPE * z0);
            float z1 = fi + fj_s[j + 32]; z1 = fmaxf(z1, NEG_SLOPE * z1);
            float z2 = fi + fj_s[j + 64]; z2 = fmaxf(z2, NEG_SLOPE * z2);
            float z3 = fi + fj_s[j + 96]; z3 = fmaxf(z3, NEG_SLOPE * z3);
            if (a0 != 0.0f) m = fmaxf(m, z0);
            if (a1 != 0.0f) m = fmaxf(m, z1);
            if (a2 != 0.0f) m = fmaxf(m, z2);
            if (a3 != 0.0f) m = fmaxf(m, z3);
        }
#pragma unroll
        for (int off = 16; off > 0; off >>= 1)
            m = fmaxf(m, __shfl_xor_sync(0xffffffffu, m, off));

        float s = 0.0f;
#pragma unroll 1
        for (int j = lane; j < NN; j += 128) {
            float a0 = adjrow[j];
            float a1 = adjrow[j + 32];
            float a2 = adjrow[j + 64];
            float a3 = adjrow[j + 96];
            float z0 = fi + fj_s[j];      z0 = fmaxf(z0, NEG_SLOPE * z0);
            float z1 = fi + fj_s[j + 32]; z1 = fmaxf(z1, NEG_SLOPE * z1);
            float z2 = fi + fj_s[j + 64]; z2 = fmaxf(z2, NEG_SLOPE * z2);
            float z3 = fi + fj_s[j + 96]; z3 = fmaxf(z3, NEG_SLOPE * z3);
            if (a0 != 0.0f) s += __expf(z0 - m);
            if (a1 != 0.0f) s += __expf(z1 - m);
            if (a2 != 0.0f) s += __expf(z2 - m);
            if (a3 != 0.0f) s += __expf(z3 - m);
        }
#pragma unroll
        for (int off = 16; off > 0; off >>= 1)
            s += __shfl_xor_sync(0xffffffffu, s, off);

        if (lane == 0) {
            m_s[r] = m;
            sinv_s[r] = (s > 0.0f) ? (1.0f / s) : 0.0f;  // empty row -> alpha all 0 (nan_to_num)
        }
    }
    __syncthreads();

    // ---- Pass 2: j-tiles of 64: load h tile, compute+store alpha, accumulate out ----
    int rg = tid >> 4;            // 0..15 -> rows rg*4 .. rg*4+3
    int dg = (tid & 15) * 4;      // dims dg .. dg+3

    unsigned long long acc[4][2];
#pragma unroll
    for (int ri = 0; ri < 4; ri++) { acc[ri][0] = 0ULL; acc[ri][1] = 0ULL; }

    const float4* hg_base = (const float4*)(g_h + (size_t)b * NN * OUT_DIM);

#pragma unroll 1
    for (int j0 = 0; j0 < NN; j0 += 64) {
        __syncthreads();  // protect h_s / alpha_t from previous tile's readers

        // load h tile [64 x 64] (1024 float4)
        {
            const float4* hg = hg_base + (size_t)j0 * (OUT_DIM / 4);
            float4* hs = (float4*)h_s;
#pragma unroll
            for (int i = 0; i < 4; i++) hs[tid + i * 256] = hg[tid + i * 256];
        }

        // alpha: warp w handles rows w*8..w*8+7, lanes over j (2 each)
#pragma unroll
        for (int rr = 0; rr < 8; rr++) {
            int r = w * 8 + rr;
            float m  = m_s[r];
            float si = sinv_s[r];
            float fi = fi_s[r];
            const float* adjrow = adj + (size_t)(i0 + r) * NN + j0;
            float* aout = alpha_out + ((size_t)(b * NN) + i0 + r) * NN + j0;
#pragma unroll
            for (int k = 0; k < 2; k++) {
                int jj = lane + 32 * k;
                float av = adjrow[jj];
                float z = fi + fj_s[j0 + jj];
                z = fmaxf(z, NEG_SLOPE * z);
                float al = 0.0f;
                if (av != 0.0f) al = __expf(z - m) * si;
                aout[jj] = al;                       // coalesced 128B store
                alpha_t[jj * 65 + r] = al;           // (jj + r) % 32 -> conflict-free
            }
        }
        __syncthreads();

        // accumulate: out[r][d] += alpha[r][jj] * h[jj][d], f32x2 packed
#pragma unroll 2
        for (int jj = 0; jj < 64; jj++) {
            const unsigned long long* hp =
                (const unsigned long long*)&h_s[jj * OUT_DIM + dg];
            unsigned long long h0 = hp[0];
            unsigned long long h1 = hp[1];
            const float* ap = &alpha_t[jj * 65 + rg * 4];
#pragma unroll
            for (int ri = 0; ri < 4; ri++) {
                float av = ap[ri];                   // broadcast within 16-thread group
                unsigned long long a2 = pack2(av, av);
                ffma2(acc[ri][0], a2, h0);
                ffma2(acc[ri][1], a2, h1);
            }
        }
    }

    // write out
#pragma unroll
    for (int ri = 0; ri < 4; ri++) {
        float o0, o1, o2, o3;
        unpack2(acc[ri][0], o0, o1);
        unpack2(acc[ri][1], o2, o3);
        size_t oidx = ((size_t)(b * NN) + i0 + rg * 4 + ri) * OUT_DIM + dg;
        *(float4*)&out[oidx] = make_float4(o0, o1, o2, o3);
    }
}

// ============================================================================
extern "C" void kernel_launch(void* const* d_in, const int* in_sizes, int n_in,
                              void* d_out, int out_size)
{
    (void)in_sizes; (void)n_in; (void)out_size;
    const float* x   = (const float*)d_in[0];   // (8, 2048, 128)
    const float* adj = (const float*)d_in[1];   // (2048, 2048)
    const float* W   = (const float*)d_in[2];   // (128, 64)
    const float* a   = (const float*)d_in[3];   // (128,)

    float* out   = (float*)d_out;                              // (8, 2048, 64)
    float* alpha = out + (size_t)BATCH * NN * OUT_DIM;         // (8, 2048, 2048)

    gat_h_kernel<<<(BATCH * NN) / 32, 256>>>(x, W, a);

    dim3 grid(NN / 64, BATCH);
    gat_main_kernel<<<grid, 256>>>(adj, out, alpha);
}

// round 4
// speedup vs baseline: 1.4628x; 1.4628x over previous
#include <cuda_runtime.h>

#define BATCH 8
#define NN 2048
#define IN_DIM 128
#define OUT_DIM 64
#define NEG_SLOPE 0.2f
#define JSPLIT 4
#define TOT (BATCH * NN * OUT_DIM)

typedef unsigned long long ULL;

// Scratch (allocation-free rule: __device__ globals)
__device__ float g_ht[BATCH * OUT_DIM * NN];     // 4 MB, h transposed: [b][d][n]
__device__ float g_fi[BATCH * NN];
__device__ float g_fj[BATCH * NN];
__device__ float g_m[BATCH * NN];
__device__ float g_sinv[BATCH * NN];
__device__ float g_out_part[JSPLIT * TOT];       // 16 MB

// ---- packed f32x2 helpers (ptxas never emits FFMA2 from C++) ----
__device__ __forceinline__ void unpack2(ULL v, float& x, float& y) {
    asm("mov.b64 {%0, %1}, %2;" : "=f"(x), "=f"(y) : "l"(v));
}
__device__ __forceinline__ void ffma2(ULL& d, ULL a, ULL b) {
    asm("fma.rn.f32x2 %0, %1, %2, %0;" : "+l"(d) : "l"(a), "l"(b));
}
__device__ __forceinline__ float neg_inf_f() { return __int_as_float(0xff800000); }

// ============================================================================
// Kernel A: h = x @ W (fp32) -> writes h TRANSPOSED to g_ht[b][d][n],
//           plus f_i = h·a[:64], f_j = h·a[64:]
// One block = 32 rows, 256 threads, each thread: 1 row x 8 dims.
// ============================================================================
__global__ void __launch_bounds__(256) gat_h_kernel(
    const float* __restrict__ x, const float* __restrict__ W, const float* __restrict__ a)
{
    __shared__ float W_s[IN_DIM * OUT_DIM];  // 32 KB
    int tid = threadIdx.x;
    {
        const float4* Wv = (const float4*)W;
        float4* Wsv = (float4*)W_s;
#pragma unroll
        for (int i = 0; i < 8; i++) Wsv[tid + i * 256] = Wv[tid + i * 256];
    }
    __syncthreads();

    int r = tid >> 3;            // 0..31 row within block
    int dg = (tid & 7) * 8;      // dim group start
    int row = blockIdx.x * 32 + r;
    const float* xrow = x + (size_t)row * IN_DIM;

    float acc[8];
#pragma unroll
    for (int d = 0; d < 8; d++) acc[d] = 0.0f;

#pragma unroll 4
    for (int k = 0; k < IN_DIM; k++) {
        float xv = __ldg(&xrow[k]);            // broadcast among the 8 dim-group threads
        const float* wr = &W_s[k * OUT_DIM + dg];
#pragma unroll
        for (int d = 0; d < 8; d++) acc[d] = fmaf(xv, wr[d], acc[d]);
    }

    // write h transposed: g_ht[(b*64 + d)*NN + n]
    int b = row >> 11;
    int n = row & (NN - 1);
#pragma unroll
    for (int d = 0; d < 8; d++)
        g_ht[((size_t)(b * OUT_DIM) + dg + d) * NN + n] = acc[d];

    // partial dots with a_i / a_j, reduce across the 8 threads of this row
    float fi = 0.0f, fj = 0.0f;
#pragma unroll
    for (int d = 0; d < 8; d++) {
        fi = fmaf(acc[d], __ldg(&a[dg + d]), fi);
        fj = fmaf(acc[d], __ldg(&a[OUT_DIM + dg + d]), fj);
    }
#pragma unroll
    for (int off = 4; off > 0; off >>= 1) {
        fi += __shfl_down_sync(0xffffffffu, fi, off);
        fj += __shfl_down_sync(0xffffffffu, fj, off);
    }
    if ((tid & 7) == 0) {
        g_fi[row] = fi;
        g_fj[row] = fj;
    }
}

// ============================================================================
// Kernel B: per-row softmax stats in ONE adj sweep.
// m_r = lrelu(fi_r + max_j fj)  (unmasked max — mathematically identical softmax,
// since lrelu is monotone and normalization cancels m; z range ~[-6,6], no underflow)
// s_r = sum_{adj!=0} exp(z - m_r);  writes g_m, g_sinv.
// Grid (32, 8): 64 rows/block, 8 warps x 8 rows.
// ============================================================================
__global__ void __launch_bounds__(256) gat_stats_kernel(const float* __restrict__ adj)
{
    __shared__ float fj_s[NN];   // 8 KB
    __shared__ float red_s[8];

    int tid = threadIdx.x, lane = tid & 31, w = tid >> 5;
    int b = blockIdx.y;
    int i0 = blockIdx.x * 64;

#pragma unroll
    for (int k = 0; k < 2; k++)
        ((float4*)fj_s)[tid + k * 256] = ((const float4*)(g_fj + (size_t)b * NN))[tid + k * 256];
    __syncthreads();

    // block-wide max of fj
    float lm = neg_inf_f();
#pragma unroll
    for (int k = 0; k < 8; k++) lm = fmaxf(lm, fj_s[tid + k * 256]);
#pragma unroll
    for (int off = 16; off > 0; off >>= 1)
        lm = fmaxf(lm, __shfl_xor_sync(0xffffffffu, lm, off));
    if (lane == 0) red_s[w] = lm;
    __syncthreads();
    float fjmax = red_s[0];
#pragma unroll
    for (int q = 1; q < 8; q++) fjmax = fmaxf(fjmax, red_s[q]);

#pragma unroll 1
    for (int rr = 0; rr < 8; rr++) {
        int r = w * 8 + rr;
        int grow = b * NN + i0 + r;
        float fi = g_fi[grow];
        float m = fi + fjmax;
        m = fmaxf(m, NEG_SLOPE * m);          // lrelu
        const float* adjrow = adj + (size_t)(i0 + r) * NN;

        float s = 0.0f;
#pragma unroll 1
        for (int j = lane; j < NN; j += 128) {
            float a0 = adjrow[j];
            float a1 = adjrow[j + 32];
            float a2 = adjrow[j + 64];
            float a3 = adjrow[j + 96];
            float z0 = fi + fj_s[j];      z0 = fmaxf(z0, NEG_SLOPE * z0);
            float z1 = fi + fj_s[j + 32]; z1 = fmaxf(z1, NEG_SLOPE * z1);
            float z2 = fi + fj_s[j + 64]; z2 = fmaxf(z2, NEG_SLOPE * z2);
            float z3 = fi + fj_s[j + 96]; z3 = fmaxf(z3, NEG_SLOPE * z3);
            if (a0 != 0.0f) s += __expf(z0 - m);
            if (a1 != 0.0f) s += __expf(z1 - m);
            if (a2 != 0.0f) s += __expf(z2 - m);
            if (a3 != 0.0f) s += __expf(z3 - m);
        }
#pragma unroll
        for (int off = 16; off > 0; off >>= 1)
            s += __shfl_xor_sync(0xffffffffu, s, off);

        if (lane == 0) {
            g_m[grow] = m;
            g_sinv[grow] = (s > 0.0f) ? (1.0f / s) : 0.0f;  // empty row -> alpha 0
        }
    }
}

// ============================================================================
// Kernel C: heavy kernel. Grid (32 i-tiles, 4 j-quarters, 8 batches) = 1024 blocks.
// Per tile: fill transposed h_t (LDS.64-friendly), compute+store alpha,
// j-paired FFMA2 accumulation (acc lanes = even/odd-j partial sums).
// Writes partial out to g_out_part[jq].
// ============================================================================
__global__ void __launch_bounds__(256) gat_acc_kernel(
    const float* __restrict__ adj, float* __restrict__ alpha_out)
{
    __shared__ float fj_s[512];             // this j-quarter
    __shared__ float fi_s[64], m_s[64], sinv_s[64];
    __shared__ float h_t[64 * 66];          // [d][jj], stride 66
    __shared__ float alpha_s[64 * 66];      // [r][jj], stride 66

    int tid = threadIdx.x, lane = tid & 31, w = tid >> 5;
    int i0 = blockIdx.x * 64;
    int jq = blockIdx.y;
    int b  = blockIdx.z;
    int jbase = jq * 512;

    ((float2*)fj_s)[tid] = ((const float2*)(g_fj + (size_t)b * NN + jbase))[tid];
    if (tid < 64) {
        int grow = b * NN + i0 + tid;
        fi_s[tid]   = g_fi[grow];
        m_s[tid]    = g_m[grow];
        sinv_s[tid] = g_sinv[grow];
    }
    __syncthreads();

    int rg  = tid >> 4;       // 0..15 -> rows rg*4 .. rg*4+3
    int dgi = tid & 15;       // dims dgi + 16*di (interleaved -> conflict-free LDS.64)

    ULL acc[4][4];
#pragma unroll
    for (int ri = 0; ri < 4; ri++)
#pragma unroll
        for (int di = 0; di < 4; di++) acc[ri][di] = 0ULL;

    const float* ht_b = g_ht + (size_t)b * OUT_DIM * NN;

#pragma unroll 1
    for (int t = 0; t < 8; t++) {
        int j0 = jbase + t * 64;
        __syncthreads();   // protect h_t/alpha_s from previous tile's readers

        // fill transposed h tile: thread covers d = w + k*8, jj-pair = 2*lane
#pragma unroll
        for (int k = 0; k < 8; k++) {
            int d = w + k * 8;
            ULL v = *(const ULL*)(ht_b + (size_t)d * NN + j0 + 2 * lane);
            *(ULL*)&h_t[d * 66 + 2 * lane] = v;
        }

        // alpha: warp w handles rows w*8..w*8+7, lanes over jj (2 each)
#pragma unroll
        for (int rr = 0; rr < 8; rr++) {
            int r = w * 8 + rr;
            float m  = m_s[r];
            float si = sinv_s[r];
            float fi = fi_s[r];
            const float* adjrow = adj + (size_t)(i0 + r) * NN + j0;
            float* aout = alpha_out + ((size_t)b * NN + i0 + r) * NN + j0;
#pragma unroll
            for (int k2 = 0; k2 < 2; k2++) {
                int jj = lane + 32 * k2;
                float av = adjrow[jj];
                float z = fi + fj_s[t * 64 + jj];
                z = fmaxf(z, NEG_SLOPE * z);
                float al = (av != 0.0f) ? (__expf(z - m) * si) : 0.0f;
                aout[jj] = al;                    // coalesced 128B store
                alpha_s[r * 66 + jj] = al;        // bank = (2r + jj)%32 -> conflict-free
            }
        }
        __syncthreads();

        // j-paired accumulate: acc[ri][di] lanes hold (even-j, odd-j) partials
#pragma unroll 2
        for (int jj = 0; jj < 64; jj += 2) {
            ULL h2[4], a2[4];
#pragma unroll
            for (int di = 0; di < 4; di++)
                h2[di] = *(const ULL*)&h_t[(dgi + 16 * di) * 66 + jj];
#pragma unroll
            for (int ri = 0; ri < 4; ri++)
                a2[ri] = *(const ULL*)&alpha_s[(rg * 4 + ri) * 66 + jj];
#pragma unroll
            for (int ri = 0; ri < 4; ri++)
#pragma unroll
                for (int di = 0; di < 4; di++)
                    ffma2(acc[ri][di], a2[ri], h2[di]);
        }
    }

    // write partial out
    float* pout = g_out_part + (size_t)jq * TOT + ((size_t)b * NN + i0) * OUT_DIM;
#pragma unroll
    for (int ri = 0; ri < 4; ri++) {
        int row = rg * 4 + ri;
#pragma unroll
        for (int di = 0; di < 4; di++) {
            float lo, hi;
            unpack2(acc[ri][di], lo, hi);
            pout[(size_t)row * OUT_DIM + dgi + 16 * di] = lo + hi;
        }
    }
}

// ============================================================================
// Kernel D: out = sum of 4 partials (float4 vectorized)
// ============================================================================
__global__ void __launch_bounds__(256) gat_reduce_kernel(float* __restrict__ out)
{
    int idx = blockIdx.x * 256 + threadIdx.x;   // float4 index, grid covers TOT/4
    const float4* p = (const float4*)g_out_part;
    const int Q4 = TOT / 4;
    float4 a0 = p[idx];
    float4 a1 = p[idx + Q4];
    float4 a2 = p[idx + 2 * Q4];
    float4 a3 = p[idx + 3 * Q4];
    ((float4*)out)[idx] = make_float4(a0.x + a1.x + a2.x + a3.x,
                                      a0.y + a1.y + a2.y + a3.y,
                                      a0.z + a1.z + a2.z + a3.z,
                                      a0.w + a1.w + a2.w + a3.w);
}

// ============================================================================
extern "C" void kernel_launch(void* const* d_in, const int* in_sizes, int n_in,
                              void* d_out, int out_size)
{
    (void)in_sizes; (void)n_in; (void)out_size;
    const float* x   = (const float*)d_in[0];   // (8, 2048, 128)
    const float* adj = (const float*)d_in[1];   // (2048, 2048)
    const float* W   = (const float*)d_in[2];   // (128, 64)
    const float* a   = (const float*)d_in[3];   // (128,)

    float* out   = (float*)d_out;                              // (8, 2048, 64)
    float* alpha = out + (size_t)BATCH * NN * OUT_DIM;         // (8, 2048, 2048)

    gat_h_kernel<<<(BATCH * NN) / 32, 256>>>(x, W, a);

    dim3 gridB(NN / 64, BATCH);
    gat_stats_kernel<<<gridB, 256>>>(adj);

    dim3 gridC(NN / 64, JSPLIT, BATCH);
    gat_acc_kernel<<<gridC, 256>>>(adj, alpha);

    gat_reduce_kernel<<<(TOT / 4) / 256, 256>>>(out);
}

// round 8
// speedup vs baseline: 1.8848x; 1.2885x over previous
#include <cuda_runtime.h>
#include <cuda_bf16.h>
#include <stdint.h>

#define BATCH 8
#define NN 2048
#define IN_DIM 128
#define OUT_DIM 64
#define NEG_SLOPE 0.2f
#define JSPLIT 4
#define TOT (BATCH * NN * OUT_DIM)

// ---- device scratch (allocation-free rule) ----
__device__ __nv_bfloat16 g_hhi[BATCH * NN * OUT_DIM];   // 2 MB, h hi part [b][n][d]
__device__ __nv_bfloat16 g_hlo[BATCH * NN * OUT_DIM];   // 2 MB, h lo part
__device__ float g_fi[BATCH * NN];
__device__ float g_fj[BATCH * NN];
__device__ float g_out_part[JSPLIT * TOT];              // 16 MB

__device__ __forceinline__ float neg_inf_f() { return __int_as_float(0xff800000); }

// ---- tensor-core helpers (sm_80+ ISA: valid on base sm_100 target) ----
__device__ __forceinline__ void ldsm_x4(uint32_t& r0, uint32_t& r1, uint32_t& r2, uint32_t& r3,
                                        uint32_t addr) {
    asm volatile("ldmatrix.sync.aligned.m8n8.x4.shared.b16 {%0,%1,%2,%3}, [%4];"
                 : "=r"(r0), "=r"(r1), "=r"(r2), "=r"(r3) : "r"(addr));
}
__device__ __forceinline__ void ldsm_x4_t(uint32_t& r0, uint32_t& r1, uint32_t& r2, uint32_t& r3,
                                          uint32_t addr) {
    asm volatile("ldmatrix.sync.aligned.m8n8.x4.trans.shared.b16 {%0,%1,%2,%3}, [%4];"
                 : "=r"(r0), "=r"(r1), "=r"(r2), "=r"(r3) : "r"(addr));
}
__device__ __forceinline__ void mma16816(float* c, const uint32_t* a, uint32_t b0, uint32_t b1) {
    asm volatile(
        "mma.sync.aligned.m16n8k16.row.col.f32.bf16.bf16.f32 "
        "{%0,%1,%2,%3}, {%4,%5,%6,%7}, {%8,%9}, {%0,%1,%2,%3};"
        : "+f"(c[0]), "+f"(c[1]), "+f"(c[2]), "+f"(c[3])
        : "r"(a[0]), "r"(a[1]), "r"(a[2]), "r"(a[3]), "r"(b0), "r"(b1));
}

// ============================================================================
// Kernel A: h = x @ W; writes h as bf16 hi/lo [b][n][d]; fi = h·a[:64]; fj = h·a[64:]
// One block = 32 rows, 256 threads, each thread: 1 row x 8 dims.
// ============================================================================
__global__ void __launch_bounds__(256) gat_h_kernel(
    const float* __restrict__ x, const float* __restrict__ W, const float* __restrict__ a)
{
    __shared__ float W_s[IN_DIM * OUT_DIM];
    int tid = threadIdx.x;
    {
        const float4* Wv = (const float4*)W;
        float4* Wsv = (float4*)W_s;
#pragma unroll
        for (int i = 0; i < 8; i++) Wsv[tid + i * 256] = Wv[tid + i * 256];
    }
    __syncthreads();

    int r = tid >> 3;
    int dg = (tid & 7) * 8;
    int row = blockIdx.x * 32 + r;
    const float* xrow = x + (size_t)row * IN_DIM;

    float acc[8];
#pragma unroll
    for (int d = 0; d < 8; d++) acc[d] = 0.0f;

#pragma unroll 4
    for (int k = 0; k < IN_DIM; k++) {
        float xv = __ldg(&xrow[k]);
        const float* wr = &W_s[k * OUT_DIM + dg];
#pragma unroll
        for (int d = 0; d < 8; d++) acc[d] = fmaf(xv, wr[d], acc[d]);
    }

    // bf16 hi/lo split, store 8 dims = one uint4 each
    {
        uint32_t uh[4], ul[4];
#pragma unroll
        for (int p = 0; p < 4; p++) {
            __nv_bfloat162 hp = __floats2bfloat162_rn(acc[2 * p], acc[2 * p + 1]);
            float l0 = acc[2 * p]     - __bfloat162float(hp.x);
            float l1 = acc[2 * p + 1] - __bfloat162float(hp.y);
            __nv_bfloat162 lp = __floats2bfloat162_rn(l0, l1);
            uh[p] = *(uint32_t*)&hp;
            ul[p] = *(uint32_t*)&lp;
        }
        size_t base = (size_t)row * OUT_DIM + dg;   // row already includes batch
        *(uint4*)(g_hhi + base) = make_uint4(uh[0], uh[1], uh[2], uh[3]);
        *(uint4*)(g_hlo + base) = make_uint4(ul[0], ul[1], ul[2], ul[3]);
    }

    float fi = 0.0f, fj = 0.0f;
#pragma unroll
    for (int d = 0; d < 8; d++) {
        fi = fmaf(acc[d], __ldg(&a[dg + d]), fi);
        fj = fmaf(acc[d], __ldg(&a[OUT_DIM + dg + d]), fj);
    }
#pragma unroll
    for (int off = 4; off > 0; off >>= 1) {
        fi += __shfl_down_sync(0xffffffffu, fi, off);
        fj += __shfl_down_sync(0xffffffffu, fj, off);
    }
    if ((tid & 7) == 0) {
        g_fi[row] = fi;
        g_fj[row] = fj;
    }
}

// ============================================================================
// Kernel B: per-row softmax stats in ONE adj sweep (unmasked-fjmax trick).
// Writes g_fi := unchanged; outputs m,sinv packed back into g_fi? No — keep
// separate arrays below.
// ============================================================================
__device__ float g_m[BATCH * NN];
__device__ float g_sinv[BATCH * NN];

__global__ void __launch_bounds__(256) gat_stats_kernel(const float* __restrict__ adj)
{
    __shared__ float fj_s[NN];   // 8 KB
    __shared__ float red_s[8];

    int tid = threadIdx.x, lane = tid & 31, w = tid >> 5;
    int b = blockIdx.y;
    int i0 = blockIdx.x * 64;

#pragma unroll
    for (int k = 0; k < 2; k++)
        ((float4*)fj_s)[tid + k * 256] = ((const float4*)(g_fj + (size_t)b * NN))[tid + k * 256];
    __syncthreads();

    float lm = neg_inf_f();
#pragma unroll
    for (int k = 0; k < 8; k++) lm = fmaxf(lm, fj_s[tid + k * 256]);
#pragma unroll
    for (int off = 16; off > 0; off >>= 1)
        lm = fmaxf(lm, __shfl_xor_sync(0xffffffffu, lm, off));
    if (lane == 0) red_s[w] = lm;
    __syncthreads();
    float fjmax = red_s[0];
#pragma unroll
    for (int q = 1; q < 8; q++) fjmax = fmaxf(fjmax, red_s[q]);

#pragma unroll 1
    for (int rr = 0; rr < 8; rr++) {
        int r = w * 8 + rr;
        int grow = b * NN + i0 + r;
        float fi = g_fi[grow];
        float m = fi + fjmax;
        m = fmaxf(m, NEG_SLOPE * m);
        const float* adjrow = adj + (size_t)(i0 + r) * NN;

        float s = 0.0f;
#pragma unroll 1
        for (int j = lane; j < NN; j += 128) {
            float a0 = adjrow[j];
            float a1 = adjrow[j + 32];
            float a2 = adjrow[j + 64];
            float a3 = adjrow[j + 96];
            float z0 = fi + fj_s[j];      z0 = fmaxf(z0, NEG_SLOPE * z0);
            float z1 = fi + fj_s[j + 32]; z1 = fmaxf(z1, NEG_SLOPE * z1);
            float z2 = fi + fj_s[j + 64]; z2 = fmaxf(z2, NEG_SLOPE * z2);
            float z3 = fi + fj_s[j + 96]; z3 = fmaxf(z3, NEG_SLOPE * z3);
            if (a0 != 0.0f) s += __expf(z0 - m);
            if (a1 != 0.0f) s += __expf(z1 - m);
            if (a2 != 0.0f) s += __expf(z2 - m);
            if (a3 != 0.0f) s += __expf(z3 - m);
        }
#pragma unroll
        for (int off = 16; off > 0; off >>= 1)
            s += __shfl_xor_sync(0xffffffffu, s, off);

        if (lane == 0) {
            g_m[grow] = m;
            g_sinv[grow] = (s > 0.0f) ? (1.0f / s) : 0.0f;
        }
    }
}

// ============================================================================
// Kernel C: grid (32 i-tiles of 64, 4 j-quarters, 8 batches) = 1024 blocks.
// Per 64x64 j-subtile: compute alpha (fp32->global, bf16 hi/lo->smem), load
// h tile (bf16 hi/lo), then mma.sync bf16 with 3-term precision split.
// Warp w: m-strip = (w%4)*16, n-half = (w/4)*32.
// ============================================================================
#define TS 72   // padded row stride in bf16 elements (144 B, conflict-free ldmatrix)

__global__ void __launch_bounds__(256) gat_acc_kernel(
    const float* __restrict__ adj, float* __restrict__ alpha_out)
{
    __shared__ float fj_s[512];
    __shared__ float fi_s[64], m_s[64], sinv_s[64];
    __shared__ __align__(16) __nv_bfloat16 a_hi_s[64 * TS];
    __shared__ __align__(16) __nv_bfloat16 a_lo_s[64 * TS];
    __shared__ __align__(16) __nv_bfloat16 h_hi_s[64 * TS];
    __shared__ __align__(16) __nv_bfloat16 h_lo_s[64 * TS];

    int tid = threadIdx.x, lane = tid & 31, w = tid >> 5;
    int i0 = blockIdx.x * 64;
    int jq = blockIdx.y;
    int b  = blockIdx.z;
    int jbase = jq * 512;

    ((float2*)fj_s)[tid] = ((const float2*)(g_fj + (size_t)b * NN + jbase))[tid];
    if (tid < 64) {
        int grow = b * NN + i0 + tid;
        fi_s[tid]   = g_fi[grow];
        m_s[tid]    = g_m[grow];
        sinv_s[tid] = g_sinv[grow];
    }

    const uint32_t aHiB = (uint32_t)__cvta_generic_to_shared(a_hi_s);
    const uint32_t aLoB = (uint32_t)__cvta_generic_to_shared(a_lo_s);
    const uint32_t hHiB = (uint32_t)__cvta_generic_to_shared(h_hi_s);
    const uint32_t hLoB = (uint32_t)__cvta_generic_to_shared(h_lo_s);
    // shared per-lane ldmatrix offset pattern (A non-trans and B trans share it)
    const uint32_t laneOff = (uint32_t)((lane & 15) * (TS * 2) + (lane >> 4) * 16);

    const int m0 = (w & 3) * 16;      // warp's m-strip
    const int nb = (w >> 2) * 32;     // warp's n-half

    float acc[4][4];
#pragma unroll
    for (int nt = 0; nt < 4; nt++)
#pragma unroll
        for (int q = 0; q < 4; q++) acc[nt][q] = 0.0f;

    // h-tile fill mapping: thread -> (row jj = tid/4, 32-byte chunk = tid%4)
    const int hrow = tid >> 2;
    const int hch  = tid & 3;

    __syncthreads();

#pragma unroll 1
    for (int t = 0; t < 8; t++) {
        const int j0 = jbase + t * 64;
        __syncthreads();   // protect smem tiles from previous iteration's readers

        // ---- h tile: [jj][d] bf16 hi/lo (B operand, row-major k x n) ----
        {
            const uint4* shi = (const uint4*)(g_hhi + ((size_t)b * NN + j0 + hrow) * OUT_DIM);
            const uint4* slo = (const uint4*)(g_hlo + ((size_t)b * NN + j0 + hrow) * OUT_DIM);
            uint4 v0 = shi[hch * 2], v1 = shi[hch * 2 + 1];
            uint4 u0 = slo[hch * 2], u1 = slo[hch * 2 + 1];
            int e = hrow * TS + hch * 16;
            *(uint4*)&h_hi_s[e]     = v0;
            *(uint4*)&h_hi_s[e + 8] = v1;
            *(uint4*)&h_lo_s[e]     = u0;
            *(uint4*)&h_lo_s[e + 8] = u1;
        }

        // ---- alpha: warp w rows w*8..w*8+7, lane covers j-pair (2*lane, 2*lane+1) ----
        {
            float2 fj2 = *(const float2*)&fj_s[t * 64 + 2 * lane];
#pragma unroll
            for (int rr = 0; rr < 8; rr++) {
                int r = w * 8 + rr;
                float2 av = *(const float2*)(adj + (size_t)(i0 + r) * NN + j0 + 2 * lane);
                float fi = fi_s[r], m = m_s[r], si = sinv_s[r];
                float z0 = fi + fj2.x; z0 = fmaxf(z0, NEG_SLOPE * z0);
                float z1 = fi + fj2.y; z1 = fmaxf(z1, NEG_SLOPE * z1);
                float al0 = (av.x != 0.0f) ? (__expf(z0 - m) * si) : 0.0f;
                float al1 = (av.y != 0.0f) ? (__expf(z1 - m) * si) : 0.0f;
                *(float2*)(alpha_out + ((size_t)b * NN + i0 + r) * NN + j0 + 2 * lane) =
                    make_float2(al0, al1);
                __nv_bfloat162 hp = __floats2bfloat162_rn(al0, al1);
                float l0 = al0 - __bfloat162float(hp.x);
                float l1 = al1 - __bfloat162float(hp.y);
                __nv_bfloat162 lp = __floats2bfloat162_rn(l0, l1);
                int e = r * TS + 2 * lane;
                *(uint32_t*)&a_hi_s[e] = *(uint32_t*)&hp;
                *(uint32_t*)&a_lo_s[e] = *(uint32_t*)&lp;
            }
        }
        __syncthreads();

        // ---- mma phase: 4 k-steps of 16 ----
#pragma unroll
        for (int ks = 0; ks < 4; ks++) {
            uint32_t ahi[4], alo[4];
            uint32_t aoff = (uint32_t)(m0 * (TS * 2)) + laneOff + (uint32_t)(ks * 32);
            ldsm_x4(ahi[0], ahi[1], ahi[2], ahi[3], aHiB + aoff);
            ldsm_x4(alo[0], alo[1], alo[2], alo[3], aLoB + aoff);
#pragma unroll
            for (int np = 0; np < 2; np++) {
                uint32_t boff = laneOff + (uint32_t)(ks * 16 * (TS * 2))
                              + (uint32_t)((nb + np * 16) * 2);
                uint32_t bh[4], bl[4];
                ldsm_x4_t(bh[0], bh[1], bh[2], bh[3], hHiB + boff);
                ldsm_x4_t(bl[0], bl[1], bl[2], bl[3], hLoB + boff);
                mma16816(acc[np * 2 + 0], ahi, bh[0], bh[1]);
                mma16816(acc[np * 2 + 0], ahi, bl[0], bl[1]);
                mma16816(acc[np * 2 + 0], alo, bh[0], bh[1]);
                mma16816(acc[np * 2 + 1], ahi, bh[2], bh[3]);
                mma16816(acc[np * 2 + 1], ahi, bl[2], bl[3]);
                mma16816(acc[np * 2 + 1], alo, bh[2], bh[3]);
            }
        }
    }

    // ---- write partial out: acc frag rows m0+lane/4 (+8), cols nt*8 + 2*(lane%4) ----
    float* pout = g_out_part + (size_t)jq * TOT + ((size_t)b * NN + i0) * OUT_DIM;
    int fr = lane >> 2;
    int fc = (lane & 3) * 2;
#pragma unroll
    for (int nt = 0; nt < 4; nt++) {
        int n0 = nb + nt * 8 + fc;
        size_t r0 = (size_t)(m0 + fr) * OUT_DIM + n0;
        size_t r1 = (size_t)(m0 + fr + 8) * OUT_DIM + n0;
        *(float2*)&pout[r0] = make_float2(acc[nt][0], acc[nt][1]);
        *(float2*)&pout[r1] = make_float2(acc[nt][2], acc[nt][3]);
    }
}

// ============================================================================
// Kernel D: out = sum of 4 partials (float4 vectorized)
// ============================================================================
__global__ void __launch_bounds__(256) gat_reduce_kernel(float* __restrict__ out)
{
    int idx = blockIdx.x * 256 + threadIdx.x;
    const float4* p = (const float4*)g_out_part;
    const int Q4 = TOT / 4;
    float4 a0 = p[idx];
    float4 a1 = p[idx + Q4];
    float4 a2 = p[idx + 2 * Q4];
    float4 a3 = p[idx + 3 * Q4];
    ((float4*)out)[idx] = make_float4(a0.x + a1.x + a2.x + a3.x,
                                      a0.y + a1.y + a2.y + a3.y,
                                      a0.z + a1.z + a2.z + a3.z,
                                      a0.w + a1.w + a2.w + a3.w);
}

// ============================================================================
extern "C" void kernel_launch(void* const* d_in, const int* in_sizes, int n_in,
                              void* d_out, int out_size)
{
    (void)in_sizes; (void)n_in; (void)out_size;
    const float* x   = (const float*)d_in[0];   // (8, 2048, 128)
    const float* adj = (const float*)d_in[1];   // (2048, 2048)
    const float* W   = (const float*)d_in[2];   // (128, 64)
    const float* a   = (const float*)d_in[3];   // (128,)

    float* out   = (float*)d_out;                              // (8, 2048, 64)
    float* alpha = out + (size_t)BATCH * NN * OUT_DIM;         // (8, 2048, 2048)

    gat_h_kernel<<<(BATCH * NN) / 32, 256>>>(x, W, a);

    dim3 gridB(NN / 64, BATCH);
    gat_stats_kernel<<<gridB, 256>>>(adj);

    dim3 gridC(NN / 64, JSPLIT, BATCH);
    gat_acc_kernel<<<gridC, 256>>>(adj, alpha);

    gat_reduce_kernel<<<(TOT / 4) / 256, 256>>>(out);
}

// round 10
// speedup vs baseline: 2.1776x; 1.1554x over previous
#include <cuda_runtime.h>
#include <cuda_fp16.h>
#include <stdint.h>

#define BATCH 8
#define NN 2048
#define IN_DIM 128
#define OUT_DIM 64
#define NEG_SLOPE 0.2f
#define JSPLIT 4
#define TOT (BATCH * NN * OUT_DIM)

// ---- device scratch (allocation-free rule) ----
__device__ __half g_h[BATCH * NN * OUT_DIM];     // 2 MB, h fp16 [b][n][d]
__device__ float g_fi[BATCH * NN];
__device__ float g_fj[BATCH * NN];
__device__ float g_m[BATCH * NN];
__device__ float g_sinv[BATCH * NN];
__device__ float g_out_part[JSPLIT * TOT];       // 16 MB

__device__ __forceinline__ float neg_inf_f() { return __int_as_float(0xff800000); }

// ---- tensor-core helpers (sm_80+ ISA: valid on base sm_100 target) ----
__device__ __forceinline__ void ldsm_x4(uint32_t& r0, uint32_t& r1, uint32_t& r2, uint32_t& r3,
                                        uint32_t addr) {
    asm volatile("ldmatrix.sync.aligned.m8n8.x4.shared.b16 {%0,%1,%2,%3}, [%4];"
                 : "=r"(r0), "=r"(r1), "=r"(r2), "=r"(r3) : "r"(addr));
}
__device__ __forceinline__ void ldsm_x4_t(uint32_t& r0, uint32_t& r1, uint32_t& r2, uint32_t& r3,
                                          uint32_t addr) {
    asm volatile("ldmatrix.sync.aligned.m8n8.x4.trans.shared.b16 {%0,%1,%2,%3}, [%4];"
                 : "=r"(r0), "=r"(r1), "=r"(r2), "=r"(r3) : "r"(addr));
}
__device__ __forceinline__ void mma16816h(float* c, const uint32_t* a, uint32_t b0, uint32_t b1) {
    asm volatile(
        "mma.sync.aligned.m16n8k16.row.col.f32.f16.f16.f32 "
        "{%0,%1,%2,%3}, {%4,%5,%6,%7}, {%8,%9}, {%0,%1,%2,%3};"
        : "+f"(c[0]), "+f"(c[1]), "+f"(c[2]), "+f"(c[3])
        : "r"(a[0]), "r"(a[1]), "r"(a[2]), "r"(a[3]), "r"(b0), "r"(b1));
}

// ============================================================================
// Kernel A: h = x @ W; writes h fp16 [b][n][d]; fi = h·a[:64]; fj = h·a[64:]
// ============================================================================
__global__ void __launch_bounds__(256) gat_h_kernel(
    const float* __restrict__ x, const float* __restrict__ W, const float* __restrict__ a)
{
    __shared__ float W_s[IN_DIM * OUT_DIM];
    int tid = threadIdx.x;
    {
        const float4* Wv = (const float4*)W;
        float4* Wsv = (float4*)W_s;
#pragma unroll
        for (int i = 0; i < 8; i++) Wsv[tid + i * 256] = Wv[tid + i * 256];
    }
    __syncthreads();

    int r = tid >> 3;
    int dg = (tid & 7) * 8;
    int row = blockIdx.x * 32 + r;
    const float* xrow = x + (size_t)row * IN_DIM;

    float acc[8];
#pragma unroll
    for (int d = 0; d < 8; d++) acc[d] = 0.0f;

#pragma unroll 4
    for (int k = 0; k < IN_DIM; k++) {
        float xv = __ldg(&xrow[k]);
        const float* wr = &W_s[k * OUT_DIM + dg];
#pragma unroll
        for (int d = 0; d < 8; d++) acc[d] = fmaf(xv, wr[d], acc[d]);
    }

    // fp16 store: 8 dims = one uint4
    {
        uint32_t uh[4];
#pragma unroll
        for (int p = 0; p < 4; p++) {
            __half2 hp = __float22half2_rn(make_float2(acc[2 * p], acc[2 * p + 1]));
            uh[p] = *(uint32_t*)&hp;
        }
        *(uint4*)(g_h + (size_t)row * OUT_DIM + dg) = make_uint4(uh[0], uh[1], uh[2], uh[3]);
    }

    float fi = 0.0f, fj = 0.0f;
#pragma unroll
    for (int d = 0; d < 8; d++) {
        fi = fmaf(acc[d], __ldg(&a[dg + d]), fi);
        fj = fmaf(acc[d], __ldg(&a[OUT_DIM + dg + d]), fj);
    }
#pragma unroll
    for (int off = 4; off > 0; off >>= 1) {
        fi += __shfl_down_sync(0xffffffffu, fi, off);
        fj += __shfl_down_sync(0xffffffffu, fj, off);
    }
    if ((tid & 7) == 0) {
        g_fi[row] = fi;
        g_fj[row] = fj;
    }
}

// ============================================================================
// Kernel B: per-row softmax stats in ONE adj sweep (unmasked-fjmax trick),
// float4 vectorized adj/fj access.
// ============================================================================
__global__ void __launch_bounds__(256) gat_stats_kernel(const float* __restrict__ adj)
{
    __shared__ float fj_s[NN];   // 8 KB
    __shared__ float red_s[8];

    int tid = threadIdx.x, lane = tid & 31, w = tid >> 5;
    int b = blockIdx.y;
    int i0 = blockIdx.x * 64;

#pragma unroll
    for (int k = 0; k < 2; k++)
        ((float4*)fj_s)[tid + k * 256] = ((const float4*)(g_fj + (size_t)b * NN))[tid + k * 256];
    __syncthreads();

    float lm = neg_inf_f();
#pragma unroll
    for (int k = 0; k < 8; k++) lm = fmaxf(lm, fj_s[tid + k * 256]);
#pragma unroll
    for (int off = 16; off > 0; off >>= 1)
        lm = fmaxf(lm, __shfl_xor_sync(0xffffffffu, lm, off));
    if (lane == 0) red_s[w] = lm;
    __syncthreads();
    float fjmax = red_s[0];
#pragma unroll
    for (int q = 1; q < 8; q++) fjmax = fmaxf(fjmax, red_s[q]);

#pragma unroll 1
    for (int rr = 0; rr < 8; rr++) {
        int r = w * 8 + rr;
        int grow = b * NN + i0 + r;
        float fi = g_fi[grow];
        float m = fi + fjmax;
        m = fmaxf(m, NEG_SLOPE * m);
        const float* adjrow = adj + (size_t)(i0 + r) * NN;

        float s = 0.0f;
#pragma unroll 1
        for (int j = lane * 4; j < NN; j += 128) {
            float4 av = *(const float4*)&adjrow[j];
            float4 fv = *(const float4*)&fj_s[j];
            float z0 = fi + fv.x; z0 = fmaxf(z0, NEG_SLOPE * z0);
            float z1 = fi + fv.y; z1 = fmaxf(z1, NEG_SLOPE * z1);
            float z2 = fi + fv.z; z2 = fmaxf(z2, NEG_SLOPE * z2);
            float z3 = fi + fv.w; z3 = fmaxf(z3, NEG_SLOPE * z3);
            if (av.x != 0.0f) s += __expf(z0 - m);
            if (av.y != 0.0f) s += __expf(z1 - m);
            if (av.z != 0.0f) s += __expf(z2 - m);
            if (av.w != 0.0f) s += __expf(z3 - m);
        }
#pragma unroll
        for (int off = 16; off > 0; off >>= 1)
            s += __shfl_xor_sync(0xffffffffu, s, off);

        if (lane == 0) {
            g_m[grow] = m;
            g_sinv[grow] = (s > 0.0f) ? (1.0f / s) : 0.0f;
        }
    }
}

// ============================================================================
// Kernel C: grid (32 i-tiles of 64, 4 j-quarters, 8 batches) = 1024 blocks.
// Per 64x64 j-subtile: alpha (fp32->global, fp16->smem), h tile fp16,
// SINGLE-term fp16 mma.sync. Warp w: m-strip=(w%4)*16, n-half=(w/4)*32.
// ============================================================================
#define TS 72   // padded row stride in fp16 elements (144 B, conflict-free ldmatrix)

__global__ void __launch_bounds__(256) gat_acc_kernel(
    const float* __restrict__ adj, float* __restrict__ alpha_out)
{
    __shared__ float fj_s[512];
    __shared__ float fi_s[64], m_s[64], sinv_s[64];
    __shared__ __align__(16) __half a_s[64 * TS];
    __shared__ __align__(16) __half h_s[64 * TS];

    int tid = threadIdx.x, lane = tid & 31, w = tid >> 5;
    int i0 = blockIdx.x * 64;
    int jq = blockIdx.y;
    int b  = blockIdx.z;
    int jbase = jq * 512;

    ((float2*)fj_s)[tid] = ((const float2*)(g_fj + (size_t)b * NN + jbase))[tid];
    if (tid < 64) {
        int grow = b * NN + i0 + tid;
        fi_s[tid]   = g_fi[grow];
        m_s[tid]    = g_m[grow];
        sinv_s[tid] = g_sinv[grow];
    }

    const uint32_t aB = (uint32_t)__cvta_generic_to_shared(a_s);
    const uint32_t hB = (uint32_t)__cvta_generic_to_shared(h_s);
    const uint32_t laneOff = (uint32_t)((lane & 15) * (TS * 2) + (lane >> 4) * 16);

    const int m0 = (w & 3) * 16;      // warp's m-strip
    const int nb = (w >> 2) * 32;     // warp's n-half

    float acc[4][4];
#pragma unroll
    for (int nt = 0; nt < 4; nt++)
#pragma unroll
        for (int q = 0; q < 4; q++) acc[nt][q] = 0.0f;

    const int hrow = tid >> 2;        // h-tile fill: row jj
    const int hch  = tid & 3;         // 16-halves chunk

    __syncthreads();

#pragma unroll 1
    for (int t = 0; t < 8; t++) {
        const int j0 = jbase + t * 64;
        __syncthreads();   // protect smem tiles from previous iteration's readers

        // ---- h tile: [jj][d] fp16 (B operand, k x n row-major) ----
        {
            const uint4* src = (const uint4*)(g_h + ((size_t)b * NN + j0 + hrow) * OUT_DIM);
            uint4 v0 = src[hch * 2], v1 = src[hch * 2 + 1];
            int e = hrow * TS + hch * 16;
            *(uint4*)&h_s[e]     = v0;
            *(uint4*)&h_s[e + 8] = v1;
        }

        // ---- alpha: warp w rows w*8..w*8+7, lane covers j-pair ----
        {
            float2 fj2 = *(const float2*)&fj_s[t * 64 + 2 * lane];
#pragma unroll
            for (int rr = 0; rr < 8; rr++) {
                int r = w * 8 + rr;
                float2 av = *(const float2*)(adj + (size_t)(i0 + r) * NN + j0 + 2 * lane);
                float fi = fi_s[r], m = m_s[r], si = sinv_s[r];
                float z0 = fi + fj2.x; z0 = fmaxf(z0, NEG_SLOPE * z0);
                float z1 = fi + fj2.y; z1 = fmaxf(z1, NEG_SLOPE * z1);
                float al0 = (av.x != 0.0f) ? (__expf(z0 - m) * si) : 0.0f;
                float al1 = (av.y != 0.0f) ? (__expf(z1 - m) * si) : 0.0f;
                *(float2*)(alpha_out + ((size_t)b * NN + i0 + r) * NN + j0 + 2 * lane) =
                    make_float2(al0, al1);
                __half2 hp = __float22half2_rn(make_float2(al0, al1));
                *(uint32_t*)&a_s[r * TS + 2 * lane] = *(uint32_t*)&hp;
            }
        }
        __syncthreads();

        // ---- mma phase: 4 k-steps of 16, single fp16 term ----
#pragma unroll
        for (int ks = 0; ks < 4; ks++) {
            uint32_t av[4];
            uint32_t aoff = (uint32_t)(m0 * (TS * 2)) + laneOff + (uint32_t)(ks * 32);
            ldsm_x4(av[0], av[1], av[2], av[3], aB + aoff);
#pragma unroll
            for (int np = 0; np < 2; np++) {
                uint32_t boff = laneOff + (uint32_t)(ks * 16 * (TS * 2))
                              + (uint32_t)((nb + np * 16) * 2);
                uint32_t bh[4];
                ldsm_x4_t(bh[0], bh[1], bh[2], bh[3], hB + boff);
                mma16816h(acc[np * 2 + 0], av, bh[0], bh[1]);
                mma16816h(acc[np * 2 + 1], av, bh[2], bh[3]);
            }
        }
    }

    // ---- write partial out ----
    float* pout = g_out_part + (size_t)jq * TOT + ((size_t)b * NN + i0) * OUT_DIM;
    int fr = lane >> 2;
    int fc = (lane & 3) * 2;
#pragma unroll
    for (int nt = 0; nt < 4; nt++) {
        int n0 = nb + nt * 8 + fc;
        size_t r0 = (size_t)(m0 + fr) * OUT_DIM + n0;
        size_t r1 = (size_t)(m0 + fr + 8) * OUT_DIM + n0;
        *(float2*)&pout[r0] = make_float2(acc[nt][0], acc[nt][1]);
        *(float2*)&pout[r1] = make_float2(acc[nt][2], acc[nt][3]);
    }
}

// ============================================================================
// Kernel D: out = sum of 4 partials (float4 vectorized)
// ============================================================================
__global__ void __launch_bounds__(256) gat_reduce_kernel(float* __restrict__ out)
{
    int idx = blockIdx.x * 256 + threadIdx.x;
    const float4* p = (const float4*)g_out_part;
    const int Q4 = TOT / 4;
    float4 a0 = p[idx];
    float4 a1 = p[idx + Q4];
    float4 a2 = p[idx + 2 * Q4];
    float4 a3 = p[idx + 3 * Q4];
    ((float4*)out)[idx] = make_float4(a0.x + a1.x + a2.x + a3.x,
                                      a0.y + a1.y + a2.y + a3.y,
                                      a0.z + a1.z + a2.z + a3.z,
                                      a0.w + a1.w + a2.w + a3.w);
}

// ============================================================================
extern "C" void kernel_launch(void* const* d_in, const int* in_sizes, int n_in,
                              void* d_out, int out_size)
{
    (void)in_sizes; (void)n_in; (void)out_size;
    const float* x   = (const float*)d_in[0];   // (8, 2048, 128)
    const float* adj = (const float*)d_in[1];   // (2048, 2048)
    const float* W   = (const float*)d_in[2];   // (128, 64)
    const float* a   = (const float*)d_in[3];   // (128,)

    float* out   = (float*)d_out;                              // (8, 2048, 64)
    float* alpha = out + (size_t)BATCH * NN * OUT_DIM;         // (8, 2048, 2048)

    gat_h_kernel<<<(BATCH * NN) / 32, 256>>>(x, W, a);

    dim3 gridB(NN / 64, BATCH);
    gat_stats_kernel<<<gridB, 256>>>(adj);

    dim3 gridC(NN / 64, JSPLIT, BATCH);
    gat_acc_kernel<<<gridC, 256>>>(adj, alpha);

    gat_reduce_kernel<<<(TOT / 4) / 256, 256>>>(out);
}

// round 11
// speedup vs baseline: 2.8402x; 1.3043x over previous
#include <cuda_runtime.h>
#include <cuda_fp16.h>
#include <stdint.h>

#define BATCH 8
#define NN 2048
#define IN_DIM 128
#define OUT_DIM 64
#define NEG_SLOPE 0.2f
#define JSPLIT 2
#define TOT (BATCH * NN * OUT_DIM)
#define NWORDS (NN / 32)          // 64 bit-words per adj row

// ---- device scratch (allocation-free rule) ----
__device__ __half g_h[BATCH * NN * OUT_DIM];       // 2 MB, h fp16 [b][n][d]
__device__ uint32_t g_adjbits[NN * NWORDS];        // 512 KB packed adjacency
__device__ float g_fi[BATCH * NN];
__device__ float g_fj[BATCH * NN];
__device__ float g_m[BATCH * NN];
__device__ float g_sinv[BATCH * NN];
__device__ float g_out_part[JSPLIT * TOT];         // 8 MB

__device__ __forceinline__ float neg_inf_f() { return __int_as_float(0xff800000); }

// ---- tensor-core helpers (sm_80+ ISA: valid on base sm_100 target) ----
__device__ __forceinline__ void ldsm_x4(uint32_t& r0, uint32_t& r1, uint32_t& r2, uint32_t& r3,
                                        uint32_t addr) {
    asm volatile("ldmatrix.sync.aligned.m8n8.x4.shared.b16 {%0,%1,%2,%3}, [%4];"
                 : "=r"(r0), "=r"(r1), "=r"(r2), "=r"(r3) : "r"(addr));
}
__device__ __forceinline__ void ldsm_x4_t(uint32_t& r0, uint32_t& r1, uint32_t& r2, uint32_t& r3,
                                          uint32_t addr) {
    asm volatile("ldmatrix.sync.aligned.m8n8.x4.trans.shared.b16 {%0,%1,%2,%3}, [%4];"
                 : "=r"(r0), "=r"(r1), "=r"(r2), "=r"(r3) : "r"(addr));
}
__device__ __forceinline__ void mma16816h(float* c, const uint32_t* a, uint32_t b0, uint32_t b1) {
    asm volatile(
        "mma.sync.aligned.m16n8k16.row.col.f32.f16.f16.f32 "
        "{%0,%1,%2,%3}, {%4,%5,%6,%7}, {%8,%9}, {%0,%1,%2,%3};"
        : "+f"(c[0]), "+f"(c[1]), "+f"(c[2]), "+f"(c[3])
        : "r"(a[0]), "r"(a[1]), "r"(a[2]), "r"(a[3]), "r"(b0), "r"(b1));
}

// ============================================================================
// Kernel P: pack adj (exact 0.0/1.0 floats) into bits. 131072 words.
// ============================================================================
__global__ void __launch_bounds__(256) gat_adjbits_kernel(const float* __restrict__ adj)
{
    int idx = blockIdx.x * 256 + threadIdx.x;          // word index
    const float4* src = (const float4*)adj + (size_t)idx * 8;
    uint32_t bits = 0;
#pragma unroll
    for (int q = 0; q < 8; q++) {
        float4 v = src[q];
        if (v.x != 0.0f) bits |= 1u << (q * 4 + 0);
        if (v.y != 0.0f) bits |= 1u << (q * 4 + 1);
        if (v.z != 0.0f) bits |= 1u << (q * 4 + 2);
        if (v.w != 0.0f) bits |= 1u << (q * 4 + 3);
    }
    g_adjbits[idx] = bits;
}

// ============================================================================
// Kernel A: h = x @ W; writes h fp16 [b][n][d]; fi = h·a[:64]; fj = h·a[64:]
// ============================================================================
__global__ void __launch_bounds__(256) gat_h_kernel(
    const float* __restrict__ x, const float* __restrict__ W, const float* __restrict__ a)
{
    __shared__ float W_s[IN_DIM * OUT_DIM];
    int tid = threadIdx.x;
    {
        const float4* Wv = (const float4*)W;
        float4* Wsv = (float4*)W_s;
#pragma unroll
        for (int i = 0; i < 8; i++) Wsv[tid + i * 256] = Wv[tid + i * 256];
    }
    __syncthreads();

    int r = tid >> 3;
    int dg = (tid & 7) * 8;
    int row = blockIdx.x * 32 + r;
    const float* xrow = x + (size_t)row * IN_DIM;

    float acc[8];
#pragma unroll
    for (int d = 0; d < 8; d++) acc[d] = 0.0f;

#pragma unroll 4
    for (int k = 0; k < IN_DIM; k++) {
        float xv = __ldg(&xrow[k]);
        const float* wr = &W_s[k * OUT_DIM + dg];
#pragma unroll
        for (int d = 0; d < 8; d++) acc[d] = fmaf(xv, wr[d], acc[d]);
    }

    {
        uint32_t uh[4];
#pragma unroll
        for (int p = 0; p < 4; p++) {
            __half2 hp = __float22half2_rn(make_float2(acc[2 * p], acc[2 * p + 1]));
            uh[p] = *(uint32_t*)&hp;
        }
        *(uint4*)(g_h + (size_t)row * OUT_DIM + dg) = make_uint4(uh[0], uh[1], uh[2], uh[3]);
    }

    float fi = 0.0f, fj = 0.0f;
#pragma unroll
    for (int d = 0; d < 8; d++) {
        fi = fmaf(acc[d], __ldg(&a[dg + d]), fi);
        fj = fmaf(acc[d], __ldg(&a[OUT_DIM + dg + d]), fj);
    }
#pragma unroll
    for (int off = 4; off > 0; off >>= 1) {
        fi += __shfl_down_sync(0xffffffffu, fi, off);
        fj += __shfl_down_sync(0xffffffffu, fj, off);
    }
    if ((tid & 7) == 0) {
        g_fi[row] = fi;
        g_fj[row] = fj;
    }
}

// ============================================================================
// Kernel B: softmax stats, one bit-masked sweep. 32 rows/block -> 512 blocks.
// 4 independent accumulators per row break the fadd chain.
// ============================================================================
__global__ void __launch_bounds__(256) gat_stats_kernel()
{
    __shared__ __align__(16) float fj_s[NN];   // 8 KB
    __shared__ float red_s[8];

    int tid = threadIdx.x, lane = tid & 31, w = tid >> 5;
    int b = blockIdx.y;
    int i0 = blockIdx.x * 32;

#pragma unroll
    for (int k = 0; k < 2; k++)
        ((float4*)fj_s)[tid + k * 256] = ((const float4*)(g_fj + (size_t)b * NN))[tid + k * 256];
    __syncthreads();

    float lm = neg_inf_f();
#pragma unroll
    for (int k = 0; k < 8; k++) lm = fmaxf(lm, fj_s[tid + k * 256]);
#pragma unroll
    for (int off = 16; off > 0; off >>= 1)
        lm = fmaxf(lm, __shfl_xor_sync(0xffffffffu, lm, off));
    if (lane == 0) red_s[w] = lm;
    __syncthreads();
    float fjmax = red_s[0];
#pragma unroll
    for (int q = 1; q < 8; q++) fjmax = fmaxf(fjmax, red_s[q]);

#pragma unroll 1
    for (int rr = 0; rr < 4; rr++) {
        int r = w * 4 + rr;
        int grow = b * NN + i0 + r;
        float fi = g_fi[grow];
        float m = fi + fjmax;
        m = fmaxf(m, NEG_SLOPE * m);
        const uint32_t* brow = g_adjbits + (size_t)(i0 + r) * NWORDS;

        float s0 = 0.0f, s1 = 0.0f, s2 = 0.0f, s3 = 0.0f;
#pragma unroll 1
        for (int j = lane * 4; j < NN; j += 128) {
            uint32_t wb = __ldg(&brow[j >> 5]);
            uint32_t b4 = (wb >> (j & 31)) & 0xFu;
            float4 fv = *(const float4*)&fj_s[j];
            float z0 = fi + fv.x; z0 = fmaxf(z0, NEG_SLOPE * z0);
            float z1 = fi + fv.y; z1 = fmaxf(z1, NEG_SLOPE * z1);
            float z2 = fi + fv.z; z2 = fmaxf(z2, NEG_SLOPE * z2);
            float z3 = fi + fv.w; z3 = fmaxf(z3, NEG_SLOPE * z3);
            if (b4 & 1u) s0 += __expf(z0 - m);
            if (b4 & 2u) s1 += __expf(z1 - m);
            if (b4 & 4u) s2 += __expf(z2 - m);
            if (b4 & 8u) s3 += __expf(z3 - m);
        }
        float s = (s0 + s1) + (s2 + s3);
#pragma unroll
        for (int off = 16; off > 0; off >>= 1)
            s += __shfl_xor_sync(0xffffffffu, s, off);

        if (lane == 0) {
            g_m[grow] = m;
            g_sinv[grow] = (s > 0.0f) ? (1.0f / s) : 0.0f;
        }
    }
}

// ============================================================================
// Kernel C: grid (32 i-tiles of 64, 2 j-halves, 8 batches) = 512 blocks.
// 128-wide j-subtiles (8 per block). Alpha: bit-masked, float4 fj, STG.128
// streaming stores. Single-term fp16 mma. Warp w: m-strip=(w%4)*16, n-half=(w/4)*32.
// ============================================================================
#define TSA 136   // a_s stride in fp16 (272 B/row; 272/4 % 32 = 4 -> conflict-free)
#define TSH 72    // h_s stride in fp16 (144 B/row)

__global__ void __launch_bounds__(256) gat_acc_kernel(float* __restrict__ alpha_out)
{
    __shared__ __align__(16) float fj_s[1024];
    __shared__ float fi_s[64], m_s[64], sinv_s[64];
    __shared__ __align__(16) __half a_s[64 * TSA];    // 17408 B
    __shared__ __align__(16) __half h_s[128 * TSH];   // 18432 B

    int tid = threadIdx.x, lane = tid & 31, w = tid >> 5;
    int i0 = blockIdx.x * 64;
    int jq = blockIdx.y;
    int b  = blockIdx.z;
    int jbase = jq * 1024;

    ((float4*)fj_s)[tid] = ((const float4*)(g_fj + (size_t)b * NN + jbase))[tid];
    if (tid < 64) {
        int grow = b * NN + i0 + tid;
        fi_s[tid]   = g_fi[grow];
        m_s[tid]    = g_m[grow];
        sinv_s[tid] = g_sinv[grow];
    }

    const uint32_t aB = (uint32_t)__cvta_generic_to_shared(a_s);
    const uint32_t hB = (uint32_t)__cvta_generic_to_shared(h_s);
    const uint32_t laneA = (uint32_t)((lane & 15) * (TSA * 2) + (lane >> 4) * 16);
    const uint32_t laneH = (uint32_t)((lane & 15) * (TSH * 2) + (lane >> 4) * 16);

    const int m0 = (w & 3) * 16;      // warp's m-strip
    const int nb = (w >> 2) * 32;     // warp's n-half

    float acc[4][4];
#pragma unroll
    for (int nt = 0; nt < 4; nt++)
#pragma unroll
        for (int q = 0; q < 4; q++) acc[nt][q] = 0.0f;

    const int hrow = tid >> 1;        // h-tile fill: row jj (0..127)
    const int hhalf = tid & 1;        // which 32-half chunk

#pragma unroll 1
    for (int t = 0; t < 8; t++) {
        const int j0 = jbase + t * 128;
        __syncthreads();   // protect smem tiles from previous iteration's readers
                           // (first iteration: also covers init loads above)

        // ---- h tile: [jj][d] fp16, 128 rows (B operand, k x n row-major) ----
        {
            const uint4* src = (const uint4*)(g_h + ((size_t)b * NN + j0 + hrow) * OUT_DIM
                                              + hhalf * 32);
            uint4* dst = (uint4*)&h_s[hrow * TSH + hhalf * 32];
#pragma unroll
            for (int q = 0; q < 4; q++) dst[q] = src[q];
        }

        // ---- alpha: warp w rows w*8..w*8+7, lane covers 4 j (bit-masked) ----
        {
            float4 fv = *(const float4*)&fj_s[t * 128 + 4 * lane];
            const int wi = (j0 >> 5) + (lane >> 3);
            const int sh = (lane & 7) * 4;
#pragma unroll
            for (int rr = 0; rr < 8; rr++) {
                int r = w * 8 + rr;
                uint32_t wb = __ldg(&g_adjbits[(size_t)(i0 + r) * NWORDS + wi]);
                uint32_t b4 = (wb >> sh) & 0xFu;
                float fi = fi_s[r], m = m_s[r], si = sinv_s[r];
                float z0 = fi + fv.x; z0 = fmaxf(z0, NEG_SLOPE * z0);
                float z1 = fi + fv.y; z1 = fmaxf(z1, NEG_SLOPE * z1);
                float z2 = fi + fv.z; z2 = fmaxf(z2, NEG_SLOPE * z2);
                float z3 = fi + fv.w; z3 = fmaxf(z3, NEG_SLOPE * z3);
                float al0 = (b4 & 1u) ? (__expf(z0 - m) * si) : 0.0f;
                float al1 = (b4 & 2u) ? (__expf(z1 - m) * si) : 0.0f;
                float al2 = (b4 & 4u) ? (__expf(z2 - m) * si) : 0.0f;
                float al3 = (b4 & 8u) ? (__expf(z3 - m) * si) : 0.0f;
                __stcs((float4*)(alpha_out + ((size_t)b * NN + i0 + r) * NN + j0 + 4 * lane),
                       make_float4(al0, al1, al2, al3));
                __half2 p0 = __float22half2_rn(make_float2(al0, al1));
                __half2 p1 = __float22half2_rn(make_float2(al2, al3));
                *(uint2*)&a_s[r * TSA + 4 * lane] =
                    make_uint2(*(uint32_t*)&p0, *(uint32_t*)&p1);
            }
        }
        __syncthreads();

        // ---- mma: 8 k-steps of 16, single fp16 term ----
#pragma unroll
        for (int ks = 0; ks < 8; ks++) {
            uint32_t av[4];
            ldsm_x4(av[0], av[1], av[2], av[3],
                    aB + (uint32_t)(m0 * (TSA * 2)) + laneA + (uint32_t)(ks * 32));
#pragma unroll
            for (int np = 0; np < 2; np++) {
                uint32_t bh[4];
                uint32_t boff = laneH + (uint32_t)(ks * 16 * (TSH * 2))
                              + (uint32_t)((nb + np * 16) * 2);
                ldsm_x4_t(bh[0], bh[1], bh[2], bh[3], hB + boff);
                mma16816h(acc[np * 2 + 0], av, bh[0], bh[1]);
                mma16816h(acc[np * 2 + 1], av, bh[2], bh[3]);
            }
        }
    }

    // ---- write partial out (streaming) ----
    float* pout = g_out_part + (size_t)jq * TOT + ((size_t)b * NN + i0) * OUT_DIM;
    int fr = lane >> 2;
    int fc = (lane & 3) * 2;
#pragma unroll
    for (int nt = 0; nt < 4; nt++) {
        int n0 = nb + nt * 8 + fc;
        __stcs((float2*)&pout[(size_t)(m0 + fr) * OUT_DIM + n0],
               make_float2(acc[nt][0], acc[nt][1]));
        __stcs((float2*)&pout[(size_t)(m0 + fr + 8) * OUT_DIM + n0],
               make_float2(acc[nt][2], acc[nt][3]));
    }
}

// ============================================================================
// Kernel D: out = sum of 2 partials (float4, streaming reads)
// ============================================================================
__global__ void __launch_bounds__(256) gat_reduce_kernel(float* __restrict__ out)
{
    int idx = blockIdx.x * 256 + threadIdx.x;
    const float4* p = (const float4*)g_out_part;
    const int Q4 = TOT / 4;
    float4 a0 = __ldcs(p + idx);
    float4 a1 = __ldcs(p + idx + Q4);
    ((float4*)out)[idx] = make_float4(a0.x + a1.x, a0.y + a1.y,
                                      a0.z + a1.z, a0.w + a1.w);
}

// ============================================================================
extern "C" void kernel_launch(void* const* d_in, const int* in_sizes, int n_in,
                              void* d_out, int out_size)
{
    (void)in_sizes; (void)n_in; (void)out_size;
    const float* x   = (const float*)d_in[0];   // (8, 2048, 128)
    const float* adj = (const float*)d_in[1];   // (2048, 2048)
    const float* W   = (const float*)d_in[2];   // (128, 64)
    const float* a   = (const float*)d_in[3];   // (128,)

    float* out   = (float*)d_out;                              // (8, 2048, 64)
    float* alpha = out + (size_t)BATCH * NN * OUT_DIM;         // (8, 2048, 2048)

    gat_adjbits_kernel<<<(NN * NWORDS) / 256, 256>>>(adj);
    gat_h_kernel<<<(BATCH * NN) / 32, 256>>>(x, W, a);

    dim3 gridB(NN / 32, BATCH);
    gat_stats_kernel<<<gridB, 256>>>();

    dim3 gridC(NN / 64, JSPLIT, BATCH);
    gat_acc_kernel<<<gridC, 256>>>(alpha);

    gat_reduce_kernel<<<(TOT / 4) / 256, 256>>>(out);
}